// round 14
// baseline (speedup 1.0000x reference)
#include <cuda_runtime.h>
#include <math.h>

// Problem constants
#define NN 51200
#define CC 200
#define HH 128
#define EE 8
#define NEDGE (NN*32)
#define EH (EE*HH)
#define K1P 224
#define NSCAN_BLK 50
#define WSPLIT_ELEMS (EE*7*128*40 + EE*4*128*40)
#define WS_BLOCKS ((WSPLIT_ELEMS + 255)/256)

// smem geometry for mma kernels (rows of 40 bf16 = 80 bytes)
#define SM_AH 0
#define SM_AL 10240
#define SM_BH 20480
#define SM_BL 30720
#define SM_STAGE 40960
#define SM_ALBS 81920
#define SMEM_MMA 82944

// -------- scratch (device globals) --------
__device__ float d_agg[NN*CC];
__device__ float d_h1[(size_t)EE*NN*HH];
__device__ float d_h2sel[NN*HH];
__device__ unsigned short d_W1h[EE*7*128*40];
__device__ unsigned short d_W1l[EE*7*128*40];
__device__ unsigned short d_W2h[EE*4*128*40];
__device__ unsigned short d_W2l[EE*4*128*40];
__device__ int   d_cnt[NN];
__device__ int   d_off[NN+1];
__device__ int   d_cur[NN];
__device__ int   d_bsum[NSCAN_BLK];
__device__ int   d_bpre[64];
__device__ int   d_barcnt[2];
__device__ int   d_ecol[NEDGE];
__device__ float d_eval[NEDGE];
__device__ int   d_topidx[NN];
__device__ float d_topval[NN];
__device__ float d_imp[EE];
__device__ float d_loadc[EE];
__device__ float d_tvsum;
__device__ float d_st1[2*EH];
__device__ float d_st2[2*EH];
__device__ float d_al1[EH], d_bsh1[EH], d_al2[EH], d_bsh2[EH];

// ======================= helpers =======================
__device__ __forceinline__ void mma_bf16(float* c, unsigned a0, unsigned a1, unsigned a2,
                                         unsigned a3, unsigned b0, unsigned b1) {
    asm volatile("mma.sync.aligned.m16n8k16.row.col.f32.bf16.bf16.f32 "
                 "{%0,%1,%2,%3}, {%4,%5,%6,%7}, {%8,%9}, {%0,%1,%2,%3};"
                 : "+f"(c[0]), "+f"(c[1]), "+f"(c[2]), "+f"(c[3])
                 : "r"(a0), "r"(a1), "r"(a2), "r"(a3), "r"(b0), "r"(b1));
}

#define LDSM_X4(r0, r1, r2, r3, addr) \
    asm volatile("ldmatrix.sync.aligned.m8n8.x4.shared.b16 {%0,%1,%2,%3}, [%4];" \
                 : "=r"(r0), "=r"(r1), "=r"(r2), "=r"(r3) : "r"(addr))

__device__ __forceinline__ void split4_store(unsigned* sh, unsigned* sl, int idx,
                                             float x0, float x1, float x2, float x3) {
    unsigned u0 = __float_as_uint(x0), u1 = __float_as_uint(x1);
    unsigned u2 = __float_as_uint(x2), u3 = __float_as_uint(x3);
    unsigned h0 = __byte_perm(u0, u1, 0x7632);
    unsigned h1 = __byte_perm(u2, u3, 0x7632);
    float l0 = x0 - __uint_as_float(u0 & 0xffff0000u);
    float l1 = x1 - __uint_as_float(u1 & 0xffff0000u);
    float l2 = x2 - __uint_as_float(u2 & 0xffff0000u);
    float l3 = x3 - __uint_as_float(u3 & 0xffff0000u);
    unsigned p0, p1;
    asm("cvt.rn.bf16x2.f32 %0, %1, %2;" : "=r"(p0) : "f"(l1), "f"(l0));
    asm("cvt.rn.bf16x2.f32 %0, %1, %2;" : "=r"(p1) : "f"(l3), "f"(l2));
    *(uint2*)(sh + idx) = make_uint2(h0, h1);
    *(uint2*)(sl + idx) = make_uint2(p0, p1);
}

// ======================= weight split-transpose =======================
__global__ void k_wsplit(const float* __restrict__ W1, const float* __restrict__ W2) {
    int idx = blockIdx.x * 256 + threadIdx.x;
    float x = 0.f;
    int dst_is_w1 = (idx < EE*7*128*40);
    int pos;
    if (dst_is_w1) {
        pos = idx;
        int kk = pos % 40;
        int h  = (pos / 40) % 128;
        int t  = pos / 5120;
        int c  = t % 7, e = t / 7;
        int k  = c * 32 + kk;
        if (kk < 32 && k < CC) x = W1[((size_t)e * CC + k) * HH + h];
    } else {
        pos = idx - EE*7*128*40;
        if (pos >= EE*4*128*40) return;
        int kk = pos % 40;
        int h  = (pos / 40) % 128;
        int t  = pos / 5120;
        int c  = t % 4, e = t / 4;
        int k  = c * 32 + kk;
        if (kk < 32) x = W2[((size_t)e * HH + k) * HH + h];
    }
    unsigned u = __float_as_uint(x);
    unsigned short hi = (unsigned short)(u >> 16);
    float lo = x - __uint_as_float(u & 0xffff0000u);
    unsigned short lob;
    {
        unsigned p;
        asm("cvt.rn.bf16x2.f32 %0, %1, %2;" : "=r"(p) : "f"(0.f), "f"(lo));
        lob = (unsigned short)(p & 0xffffu);
    }
    if (dst_is_w1) { d_W1h[pos] = hi; d_W1l[pos] = lob; }
    else           { d_W2h[pos] = hi; d_W2l[pos] = lob; }
}

// ======================= fused count + scan + scatter (cooperative) =======================
__device__ __forceinline__ void grid_bar(int which) {
    __syncthreads();
    if (threadIdx.x == 0) {
        __threadfence();
        atomicAdd(&d_barcnt[which], 1);
        while (atomicAdd(&d_barcnt[which], 0) < NSCAN_BLK) {}
        __threadfence();
    }
    __syncthreads();
}

__global__ __launch_bounds__(1024) void k_csr(const int* __restrict__ rows,
                                              const int* __restrict__ cols,
                                              const float* __restrict__ vals) {
    __shared__ int ws[32];
    __shared__ int sbpre[64];
    int b = blockIdx.x, t = threadIdx.x;
    int gid = b * 1024 + t;
    int lane = t & 31, w = t >> 5;

    // phase 1: count (d_cnt starts 0: zero-init at load, self-zeroed each replay below)
#pragma unroll 4
    for (int it = 0; it < 32; it++)
        atomicAdd(&d_cnt[rows[gid + it*NN]], 1);
    grid_bar(0);

    // phase 2: per-block scan + accumulator zeroing
    int x = d_cnt[gid];
    d_cnt[gid] = 0;
    d_cur[gid] = 0;
    if (gid < 2*EH) { d_st1[gid] = 0.f; d_st2[gid] = 0.f; }
    if (gid < EE) { d_imp[gid] = 0.f; d_loadc[gid] = 0.f; }
    if (gid == 0) { d_tvsum = 0.f; d_off[NN] = 0; }
    int s = x;
#pragma unroll
    for (int o = 1; o < 32; o <<= 1) {
        int y = __shfl_up_sync(0xffffffffu, s, o);
        if (lane >= o) s += y;
    }
    if (lane == 31) ws[w] = s;
    __syncthreads();
    if (w == 0) {
        int ss = ws[lane];
#pragma unroll
        for (int o = 1; o < 32; o <<= 1) {
            int y = __shfl_up_sync(0xffffffffu, ss, o);
            if (lane >= o) ss += y;
        }
        ws[lane] = ss;
    }
    __syncthreads();
    int incl = s + (w ? ws[w-1] : 0);
    d_off[gid] = incl - x;            // exclusive within block
    if (t == 1023) d_bsum[b] = incl;
    grid_bar(1);

    // phase 3: every block computes the block-prefix table locally
    if (t < 64) {
        int xb = (t < NSCAN_BLK) ? d_bsum[t] : 0;
        int sb = xb;
#pragma unroll
        for (int o = 1; o < 32; o <<= 1) {
            int y = __shfl_up_sync(0xffffffffu, sb, o);
            if (lane >= o) sb += y;
        }
        if (lane == 31) ws[w] = sb;
    }
    __syncthreads();
    if (t < 64) {
        int xb = (t < NSCAN_BLK) ? d_bsum[t] : 0;
        int sb2 = sbpre[0];  // placate compiler; recompute below
        (void)sb2;
        int sb = xb;
#pragma unroll
        for (int o = 1; o < 32; o <<= 1) {
            int y = __shfl_up_sync(0xffffffffu, sb, o);
            if (lane >= o) sb += y;
        }
        if (w == 1) sb += ws[0];
        sbpre[t] = sb - xb;
        if (b == 0) d_bpre[t] = sb - xb;   // publish for k_agg
    }
    __syncthreads();

    // phase 4: scatter
#pragma unroll 4
    for (int it = 0; it < 32; it++) {
        int eidx = gid + it*NN;
        int r = rows[eidx];
        int p = atomicAdd(&d_cur[r], 1);
        int d = d_off[r] + sbpre[r >> 10] + p;
        d_ecol[d] = cols[eidx];
        d_eval[d] = vals[eidx];
    }
}

// ======================= aggregation =======================
__global__ void k_agg(const float* __restrict__ v) {
    int tid = threadIdx.x;
    if (blockIdx.x == 0 && tid < 2) d_barcnt[tid] = 0;   // reset csr grid barriers for replay
    int w = tid >> 5, lane = tid & 31;
    int n = blockIdx.x * 8 + w;
    float acc[7];
#pragma unroll
    for (int j = 0; j < 7; j++) acc[j] = 0.f;
    int s = d_off[n] + d_bpre[n >> 10];
    int e = d_off[n + 1] + d_bpre[(n + 1) >> 10];
    int k = s;
    for (; k + 3 < e; k += 4) {
        int c0 = d_ecol[k],   c1 = d_ecol[k+1], c2 = d_ecol[k+2], c3 = d_ecol[k+3];
        float v0 = d_eval[k], v1 = d_eval[k+1];
        float v2 = d_eval[k+2], v3 = d_eval[k+3];
        const float* p0 = v + (size_t)c0 * CC + lane;
        const float* p1 = v + (size_t)c1 * CC + lane;
        const float* p2 = v + (size_t)c2 * CC + lane;
        const float* p3 = v + (size_t)c3 * CC + lane;
#pragma unroll
        for (int j = 0; j < 6; j++)
            acc[j] += v0 * __ldg(p0 + 32*j) + v1 * __ldg(p1 + 32*j)
                    + v2 * __ldg(p2 + 32*j) + v3 * __ldg(p3 + 32*j);
        if (lane < 8)
            acc[6] += v0 * __ldg(p0 + 192) + v1 * __ldg(p1 + 192)
                    + v2 * __ldg(p2 + 192) + v3 * __ldg(p3 + 192);
    }
    for (; k < e; k++) {
        int c0 = d_ecol[k]; float v0 = d_eval[k];
        const float* p0 = v + (size_t)c0 * CC + lane;
#pragma unroll
        for (int j = 0; j < 6; j++) acc[j] += v0 * __ldg(p0 + 32*j);
        if (lane < 8) acc[6] += v0 * __ldg(p0 + 192);
    }
    float* op = d_agg + (size_t)n * CC + lane;
#pragma unroll
    for (int j = 0; j < 6; j++) op[32*j] = acc[j];
    if (lane < 8) op[192] = acc[6];
}

__global__ void k_gate(const float* __restrict__ v, const float* __restrict__ gW,
                       const float* __restrict__ gb) {
    __shared__ float sW[CC*EE];
    __shared__ float sImp[EE], sLoad[EE], sTv;
    int tid = threadIdx.x;
    for (int i = tid; i < CC*EE; i += 256) sW[i] = gW[i];
    if (tid < EE) { sImp[tid] = 0.f; sLoad[tid] = 0.f; }
    if (tid == 0) sTv = 0.f;
    __syncthreads();
    int w = tid >> 5, lane = tid & 31;
    int n = blockIdx.x * 8 + w;
    float acc[EE];
#pragma unroll
    for (int e = 0; e < EE; e++) acc[e] = 0.f;
    for (int c = lane; c < CC; c += 32) {
        float vv = v[n*CC + c];
#pragma unroll
        for (int e = 0; e < EE; e++) acc[e] += vv * sW[c*EE + e];
    }
#pragma unroll
    for (int e = 0; e < EE; e++)
        for (int o = 16; o; o >>= 1) acc[e] += __shfl_xor_sync(0xffffffffu, acc[e], o);
    if (lane == 0) {
        float lg[EE];
        float lm = -1e30f; int li = 0;
#pragma unroll
        for (int e = 0; e < EE; e++) {
            lg[e] = acc[e] + gb[e];
            if (lg[e] > lm) { lm = lg[e]; li = e; }
        }
        float sum = 0.f; float p[EE];
#pragma unroll
        for (int e = 0; e < EE; e++) { p[e] = expf(lg[e] - lm); sum += p[e]; }
        float inv = 1.f / sum;
        d_topidx[n] = li;
        d_topval[n] = inv;
#pragma unroll
        for (int e = 0; e < EE; e++) atomicAdd(&sImp[e], p[e] * inv);
        atomicAdd(&sLoad[li], 1.f);
        atomicAdd(&sTv, inv);
    }
    __syncthreads();
    if (tid < EE) { atomicAdd(&d_imp[tid], sImp[tid]); atomicAdd(&d_loadc[tid], sLoad[tid]); }
    if (tid == 0) atomicAdd(&d_tvsum, sTv);
}

// ======================= mma consume: ldmatrix + 3x bf16-split =======================
__device__ __forceinline__ void mma_consume(unsigned smem_u, int stage, int wm, int wn,
                                            int lane, float acc[4][4][4]) {
    unsigned st = smem_u + (unsigned)stage * SM_STAGE;
    unsigned lrow = (unsigned)(lane & 15) * 80u + (unsigned)(lane >> 4) * 16u;
    unsigned aB  = st + SM_AH + (unsigned)(wm*64) * 80u + lrow;
    unsigned aBL = st + SM_AL + (unsigned)(wm*64) * 80u + lrow;
    unsigned bB  = st + SM_BH + (unsigned)(wn*32) * 80u + lrow;
    unsigned bBL = st + SM_BL + (unsigned)(wn*32) * 80u + lrow;
#pragma unroll
    for (int s = 0; s < 2; s++) {
        unsigned kb = (unsigned)s * 32u;
        unsigned ah[4][4], al[4][4], bh[4][2], bl[4][2];
#pragma unroll
        for (int i = 0; i < 4; i++) {
            LDSM_X4(ah[i][0], ah[i][1], ah[i][2], ah[i][3], aB  + (unsigned)i*1280u + kb);
            LDSM_X4(al[i][0], al[i][1], al[i][2], al[i][3], aBL + (unsigned)i*1280u + kb);
        }
#pragma unroll
        for (int jp = 0; jp < 2; jp++) {
            unsigned r0, r1, r2, r3;
            LDSM_X4(r0, r1, r2, r3, bB + (unsigned)jp*1280u + kb);
            bh[jp*2][0] = r0; bh[jp*2+1][0] = r1; bh[jp*2][1] = r2; bh[jp*2+1][1] = r3;
            LDSM_X4(r0, r1, r2, r3, bBL + (unsigned)jp*1280u + kb);
            bl[jp*2][0] = r0; bl[jp*2+1][0] = r1; bl[jp*2][1] = r2; bl[jp*2+1][1] = r3;
        }
#pragma unroll
        for (int j = 0; j < 4; j++) {
#pragma unroll
            for (int i = 0; i < 4; i++)
                mma_bf16(acc[i][j], ah[i][0], ah[i][1], ah[i][2], ah[i][3], bh[j][0], bh[j][1]);
#pragma unroll
            for (int i = 0; i < 4; i++)
                mma_bf16(acc[i][j], al[i][0], al[i][1], al[i][2], al[i][3], bh[j][0], bh[j][1]);
#pragma unroll
            for (int i = 0; i < 4; i++)
                mma_bf16(acc[i][j], ah[i][0], ah[i][1], ah[i][2], ah[i][3], bl[j][0], bl[j][1]);
        }
    }
}

// ======================= GEMM1 =======================
__global__ __launch_bounds__(256, 2) void k_mma1(const float* __restrict__ v,
                                                 const float* __restrict__ eps) {
    extern __shared__ char smem[];
    unsigned smem_u = (unsigned)__cvta_generic_to_shared(smem);
    int tid = threadIdx.x, wid = tid >> 5, lane = tid & 31;
    int e = blockIdx.y, n0 = blockIdx.x * 128;
    int wm = wid & 1, wn = wid >> 1;
    float s = 1.f + __ldg(eps + e);

    int r = tid >> 1, c0 = (tid & 1) * 16;
    const float* ap = d_agg + (size_t)(n0 + r) * CC;
    const float* vp = v     + (size_t)(n0 + r) * CC;

    float acc[4][4][4];
#pragma unroll
    for (int i = 0; i < 4; i++)
#pragma unroll
        for (int j = 0; j < 4; j++)
#pragma unroll
            for (int q = 0; q < 4; q++) acc[i][j][q] = 0.f;

#define PRODUCE1(cc) do {                                                         \
    int stg = (cc) & 1;                                                           \
    unsigned* sAh = (unsigned*)(smem + stg*SM_STAGE + SM_AH);                     \
    unsigned* sAl = (unsigned*)(smem + stg*SM_STAGE + SM_AL);                     \
    uint4* sBh4 = (uint4*)(smem + stg*SM_STAGE + SM_BH);                          \
    uint4* sBl4 = (uint4*)(smem + stg*SM_STAGE + SM_BL);                          \
    int kc = (cc) * 32;                                                           \
    _Pragma("unroll")                                                             \
    for (int g4 = 0; g4 < 4; g4++) {                                              \
        int k = kc + c0 + g4*4;                                                   \
        int idx = r*20 + ((c0 + g4*4) >> 1);                                      \
        float x0, x1, x2, x3;                                                     \
        if (k < CC) {                                                             \
            float4 a4 = *(const float4*)(ap + k);                                 \
            float4 v4 = *(const float4*)(vp + k);                                 \
            x0 = a4.x + s*v4.x; x1 = a4.y + s*v4.y;                               \
            x2 = a4.z + s*v4.z; x3 = a4.w + s*v4.w;                               \
        } else { x0 = x1 = x2 = x3 = 0.f; }                                       \
        split4_store(sAh, sAl, idx, x0, x1, x2, x3);                              \
    }                                                                             \
    const uint4* gbh = (const uint4*)d_W1h + (size_t)(e*7 + (cc)) * 640;          \
    const uint4* gbl = (const uint4*)d_W1l + (size_t)(e*7 + (cc)) * 640;          \
    _Pragma("unroll")                                                             \
    for (int ii = 0; ii < 3; ii++) {                                              \
        int i2 = tid + ii*256;                                                    \
        if (i2 < 640) { sBh4[i2] = __ldg(gbh + i2); sBl4[i2] = __ldg(gbl + i2); } \
    }                                                                             \
} while (0)

    PRODUCE1(0);
    __syncthreads();
    for (int c = 0; c < 7; c++) {
        if (c + 1 < 7) PRODUCE1(c + 1);
        mma_consume(smem_u, c & 1, wm, wn, lane, acc);
        __syncthreads();
    }
#undef PRODUCE1

    // epilogue: store h1, BN stats (bias omitted: cancels in BatchNorm)
    int g = lane >> 2, t = lane & 3;
    float sv[4][2], sq[4][2];
#pragma unroll
    for (int j = 0; j < 4; j++) { sv[j][0]=sv[j][1]=sq[j][0]=sq[j][1]=0.f; }
#pragma unroll
    for (int i = 0; i < 4; i++) {
        int row0 = n0 + wm*64 + i*16 + g;
#pragma unroll
        for (int j = 0; j < 4; j++) {
            float v0 = acc[i][j][0], v1 = acc[i][j][1];
            float v2 = acc[i][j][2], v3 = acc[i][j][3];
            int col = wn*32 + j*8 + 2*t;
            *(float2*)(d_h1 + ((size_t)e*NN + row0)*HH + col)     = make_float2(v0, v1);
            *(float2*)(d_h1 + ((size_t)e*NN + row0 + 8)*HH + col) = make_float2(v2, v3);
            sv[j][0] += v0 + v2; sv[j][1] += v1 + v3;
            sq[j][0] += v0*v0 + v2*v2; sq[j][1] += v1*v1 + v3*v3;
        }
    }
#pragma unroll
    for (int j = 0; j < 4; j++)
#pragma unroll
        for (int p = 0; p < 2; p++) {
#pragma unroll
            for (int o = 4; o < 32; o <<= 1) {
                sv[j][p] += __shfl_xor_sync(0xffffffffu, sv[j][p], o);
                sq[j][p] += __shfl_xor_sync(0xffffffffu, sq[j][p], o);
            }
        }
    if (g == 0) {
#pragma unroll
        for (int j = 0; j < 4; j++)
#pragma unroll
            for (int p = 0; p < 2; p++) {
                int col = wn*32 + j*8 + 2*t + p;
                atomicAdd(&d_st1[e*HH + col], sv[j][p]);
                atomicAdd(&d_st1[EH + e*HH + col], sq[j][p]);
            }
    }
}

__global__ void k_fin1(const float* __restrict__ g1, const float* __restrict__ be1) {
    int i = blockIdx.x * 256 + threadIdx.x;
    if (i >= EH) return;
    float mean = d_st1[i] / (float)NN;
    float var  = d_st1[EH + i] / (float)NN - mean * mean;
    float al = g1[i] * rsqrtf(var + 1e-5f);
    d_al1[i]  = al;
    d_bsh1[i] = be1[i] - mean * al;
}

// ======================= GEMM2 =======================
__global__ __launch_bounds__(256, 2) void k_mma2() {
    extern __shared__ char smem[];
    unsigned smem_u = (unsigned)__cvta_generic_to_shared(smem);
    int tid = threadIdx.x, wid = tid >> 5, lane = tid & 31;
    int e = blockIdx.y, n0 = blockIdx.x * 128;
    int wm = wid & 1, wn = wid >> 1;

    float* sAlv = (float*)(smem + SM_ALBS);
    float* sBsv = sAlv + 128;
    if (tid < 128) { sAlv[tid] = d_al1[e*HH + tid]; sBsv[tid] = d_bsh1[e*HH + tid]; }
    __syncthreads();

    int r = tid >> 1, c0 = (tid & 1) * 16;
    const float* hp = d_h1 + ((size_t)e * NN + n0 + r) * HH;

    float acc[4][4][4];
#pragma unroll
    for (int i = 0; i < 4; i++)
#pragma unroll
        for (int j = 0; j < 4; j++)
#pragma unroll
            for (int q = 0; q < 4; q++) acc[i][j][q] = 0.f;

#define PRODUCE2(cc) do {                                                         \
    int stg = (cc) & 1;                                                           \
    unsigned* sAh = (unsigned*)(smem + stg*SM_STAGE + SM_AH);                     \
    unsigned* sAl = (unsigned*)(smem + stg*SM_STAGE + SM_AL);                     \
    uint4* sBh4 = (uint4*)(smem + stg*SM_STAGE + SM_BH);                          \
    uint4* sBl4 = (uint4*)(smem + stg*SM_STAGE + SM_BL);                          \
    int kc = (cc) * 32;                                                           \
    _Pragma("unroll")                                                             \
    for (int g4 = 0; g4 < 4; g4++) {                                              \
        int k = kc + c0 + g4*4;                                                   \
        int idx = r*20 + ((c0 + g4*4) >> 1);                                      \
        float4 x4 = *(const float4*)(hp + k);                                     \
        float4 al = *(const float4*)(sAlv + k);                                   \
        float4 bs = *(const float4*)(sBsv + k);                                   \
        float x0 = fmaxf(al.x * x4.x + bs.x, 0.f);                                \
        float x1 = fmaxf(al.y * x4.y + bs.y, 0.f);                                \
        float x2 = fmaxf(al.z * x4.z + bs.z, 0.f);                                \
        float x3 = fmaxf(al.w * x4.w + bs.w, 0.f);                                \
        split4_store(sAh, sAl, idx, x0, x1, x2, x3);                              \
    }                                                                             \
    const uint4* gbh = (const uint4*)d_W2h + (size_t)(e*4 + (cc)) * 640;          \
    const uint4* gbl = (const uint4*)d_W2l + (size_t)(e*4 + (cc)) * 640;          \
    _Pragma("unroll")                                                             \
    for (int ii = 0; ii < 3; ii++) {                                              \
        int i2 = tid + ii*256;                                                    \
        if (i2 < 640) { sBh4[i2] = __ldg(gbh + i2); sBl4[i2] = __ldg(gbl + i2); } \
    }                                                                             \
} while (0)

    PRODUCE2(0);
    __syncthreads();
    for (int c = 0; c < 4; c++) {
        if (c + 1 < 4) PRODUCE2(c + 1);
        mma_consume(smem_u, c & 1, wm, wn, lane, acc);
        __syncthreads();
    }
#undef PRODUCE2

    int g = lane >> 2, t = lane & 3;
    float sv[4][2], sq[4][2];
#pragma unroll
    for (int j = 0; j < 4; j++) { sv[j][0]=sv[j][1]=sq[j][0]=sq[j][1]=0.f; }
#pragma unroll
    for (int i = 0; i < 4; i++) {
        int row0 = n0 + wm*64 + i*16 + g;
        bool sel0 = (d_topidx[row0] == e);
        bool sel8 = (d_topidx[row0 + 8] == e);
#pragma unroll
        for (int j = 0; j < 4; j++) {
            float v0 = acc[i][j][0], v1 = acc[i][j][1];
            float v2 = acc[i][j][2], v3 = acc[i][j][3];
            int col = wn*32 + j*8 + 2*t;
            if (sel0) *(float2*)(d_h2sel + (size_t)row0*HH + col)       = make_float2(v0, v1);
            if (sel8) *(float2*)(d_h2sel + (size_t)(row0 + 8)*HH + col) = make_float2(v2, v3);
            sv[j][0] += v0 + v2; sv[j][1] += v1 + v3;
            sq[j][0] += v0*v0 + v2*v2; sq[j][1] += v1*v1 + v3*v3;
        }
    }
#pragma unroll
    for (int j = 0; j < 4; j++)
#pragma unroll
        for (int p = 0; p < 2; p++) {
#pragma unroll
            for (int o = 4; o < 32; o <<= 1) {
                sv[j][p] += __shfl_xor_sync(0xffffffffu, sv[j][p], o);
                sq[j][p] += __shfl_xor_sync(0xffffffffu, sq[j][p], o);
            }
        }
    if (g == 0) {
#pragma unroll
        for (int j = 0; j < 4; j++)
#pragma unroll
            for (int p = 0; p < 2; p++) {
                int col = wn*32 + j*8 + 2*t + p;
                atomicAdd(&d_st2[e*HH + col], sv[j][p]);
                atomicAdd(&d_st2[EH + e*HH + col], sq[j][p]);
            }
    }
}

__global__ void k_fin2(const float* __restrict__ g2, const float* __restrict__ be2,
                       float* __restrict__ out, int out_size) {
    int i = blockIdx.x * 256 + threadIdx.x;
    if (i < EH) {
        float mean = d_st2[i] / (float)NN;
        float var  = d_st2[EH + i] / (float)NN - mean * mean;
        float al = g2[i] * rsqrtf(var + 1e-5f);
        d_al2[i]  = al;
        d_bsh2[i] = be2[i] - mean * al;
    }
    if (i == 0) {
        float bal = 0.f;
        for (int e = 0; e < EE; e++)
            bal += (d_imp[e] / (float)NN) * (d_loadc[e] / (float)NN);
        bal *= 0.01f * (float)EE;
        float spa = -0.01f * d_tvsum / (float)NN;
        if (out_size >= NN*HH + 2) {
            out[NN*HH]     = bal;
            out[NN*HH + 1] = spa;
        }
    }
}

__global__ void k_comb(float* __restrict__ out) {
    int idx = blockIdx.x * 256 + threadIdx.x;
    int n = idx >> 7, h = idx & 127;
    int e = d_topidx[n];
    float x = d_h2sel[idx];
    float r = fmaxf(d_al2[e*HH + h] * x + d_bsh2[e*HH + h], 0.f);
    out[idx] = d_topval[n] * r;
}

extern "C" void kernel_launch(void* const* d_in, const int* in_sizes, int n_in,
                              void* d_out, int out_size) {
    (void)in_sizes; (void)n_in;
    const float* v     = (const float*)d_in[0];
    const int*   arows = (const int*)  d_in[1];
    const int*   acols = (const int*)  d_in[2];
    const float* avals = (const float*)d_in[3];
    const float* gW    = (const float*)d_in[4];
    const float* gb    = (const float*)d_in[5];
    const float* eps   = (const float*)d_in[6];
    const float* W1    = (const float*)d_in[7];
    const float* g1    = (const float*)d_in[9];
    const float* be1   = (const float*)d_in[10];
    const float* W2    = (const float*)d_in[11];
    const float* g2    = (const float*)d_in[13];
    const float* be2   = (const float*)d_in[14];
    float* out = (float*)d_out;

    cudaFuncSetAttribute(k_mma1, cudaFuncAttributeMaxDynamicSharedMemorySize, SMEM_MMA);
    cudaFuncSetAttribute(k_mma2, cudaFuncAttributeMaxDynamicSharedMemorySize, SMEM_MMA);

    // order chosen so the profiled launch (index 3) is k_mma1
    k_wsplit<<<WS_BLOCKS, 256>>>(W1, W2);                                  // 0
    k_csr<<<NSCAN_BLK, 1024>>>(arows, acols, avals);                       // 1
    k_agg<<<NN/8, 256>>>(v);                                               // 2
    {
        dim3 g(NN/128, EE);
        k_mma1<<<g, 256, SMEM_MMA>>>(v, eps);                              // 3  <- profiled
    }
    k_gate<<<NN/8, 256>>>(v, gW, gb);                                      // 4
    k_fin1<<<(EH + 255)/256, 256>>>(g1, be1);                              // 5
    {
        dim3 g(NN/128, EE);
        k_mma2<<<g, 256, SMEM_MMA>>>();                                    // 6
    }
    k_fin2<<<(EH + 255)/256, 256>>>(g2, be2, out, out_size);               // 7
    k_comb<<<(NN*HH)/256, 256>>>(out);                                     // 8
}

// round 16
// speedup vs baseline: 1.0720x; 1.0720x over previous
#include <cuda_runtime.h>
#include <math.h>

// Problem constants
#define NN 51200
#define CC 200
#define HH 128
#define EE 8
#define NEDGE (NN*32)
#define EH (EE*HH)
#define NSCAN_BLK 50
#define WSPLIT_ELEMS (EE*7*128*40 + EE*4*128*40)
#define TR_BLOCKS ((WSPLIT_ELEMS + 255)/256)
#define CNT_BLOCKS (NEDGE/256)

// smem geometry for mma kernels (rows of 40 bf16 = 80 bytes)
#define SM_AH 0
#define SM_AL 10240
#define SM_BH 20480
#define SM_BL 30720
#define SM_STAGE 40960
#define SM_ALBS 81920
#define SMEM_MMA 82944

// -------- scratch (device globals) --------
__device__ float d_agg[NN*CC];
__device__ float d_h1[(size_t)EE*NN*HH];
__device__ float d_h2sel[NN*HH];
__device__ unsigned short d_W1h[EE*7*128*40];
__device__ unsigned short d_W1l[EE*7*128*40];
__device__ unsigned short d_W2h[EE*4*128*40];
__device__ unsigned short d_W2l[EE*4*128*40];
__device__ int   d_cnt[NN];
__device__ int   d_off[NN+1];
__device__ int   d_cur[NN];
__device__ int   d_bsum[NSCAN_BLK];
__device__ int   d_bpre[64];
__device__ int   d_scancnt;
__device__ int   d_ecol[NEDGE];
__device__ float d_eval[NEDGE];
__device__ int   d_topidx[NN];
__device__ float d_topval[NN];
__device__ float d_imp[EE];
__device__ float d_loadc[EE];
__device__ float d_tvsum;
__device__ float d_st1[2*EH];
__device__ float d_st2[2*EH];
__device__ float d_al1[EH], d_bsh1[EH], d_al2[EH], d_bsh2[EH];

// ======================= helpers =======================
__device__ __forceinline__ void mma_bf16(float* c, unsigned a0, unsigned a1, unsigned a2,
                                         unsigned a3, unsigned b0, unsigned b1) {
    asm volatile("mma.sync.aligned.m16n8k16.row.col.f32.bf16.bf16.f32 "
                 "{%0,%1,%2,%3}, {%4,%5,%6,%7}, {%8,%9}, {%0,%1,%2,%3};"
                 : "+f"(c[0]), "+f"(c[1]), "+f"(c[2]), "+f"(c[3])
                 : "r"(a0), "r"(a1), "r"(a2), "r"(a3), "r"(b0), "r"(b1));
}

#define LDSM_X4(r0, r1, r2, r3, addr) \
    asm volatile("ldmatrix.sync.aligned.m8n8.x4.shared.b16 {%0,%1,%2,%3}, [%4];" \
                 : "=r"(r0), "=r"(r1), "=r"(r2), "=r"(r3) : "r"(addr))

#define CP_ASYNC16(saddr, gptr) \
    asm volatile("cp.async.cg.shared.global [%0], [%1], 16;" :: "r"(saddr), "l"(gptr))
#define CP_COMMIT() asm volatile("cp.async.commit_group;" ::: "memory")
#define CP_WAIT0()  asm volatile("cp.async.wait_group 0;" ::: "memory")

__device__ __forceinline__ void split4_store(unsigned* sh, unsigned* sl, int idx,
                                             float x0, float x1, float x2, float x3) {
    unsigned u0 = __float_as_uint(x0), u1 = __float_as_uint(x1);
    unsigned u2 = __float_as_uint(x2), u3 = __float_as_uint(x3);
    unsigned h0 = __byte_perm(u0, u1, 0x7632);
    unsigned h1 = __byte_perm(u2, u3, 0x7632);
    float l0 = x0 - __uint_as_float(u0 & 0xffff0000u);
    float l1 = x1 - __uint_as_float(u1 & 0xffff0000u);
    float l2 = x2 - __uint_as_float(u2 & 0xffff0000u);
    float l3 = x3 - __uint_as_float(u3 & 0xffff0000u);
    unsigned p0, p1;
    asm("cvt.rn.bf16x2.f32 %0, %1, %2;" : "=r"(p0) : "f"(l1), "f"(l0));
    asm("cvt.rn.bf16x2.f32 %0, %1, %2;" : "=r"(p1) : "f"(l3), "f"(l2));
    *(uint2*)(sh + idx) = make_uint2(h0, h1);
    *(uint2*)(sl + idx) = make_uint2(p0, p1);
}

// ======================= fused count + weight split-transpose =======================
__global__ void k_pre(const int* __restrict__ rows, const float* __restrict__ W1,
                      const float* __restrict__ W2) {
    int b = blockIdx.x;
    if (b < CNT_BLOCKS) {
        int i = b * 256 + threadIdx.x;
        atomicAdd(&d_cnt[rows[i]], 1);
        return;
    }
    int idx = (b - CNT_BLOCKS) * 256 + threadIdx.x;
    float x = 0.f;
    int dst_is_w1 = (idx < EE*7*128*40);
    int pos;
    if (dst_is_w1) {
        pos = idx;
        int kk = pos % 40;
        int h  = (pos / 40) % 128;
        int t  = pos / 5120;
        int c  = t % 7, e = t / 7;
        int k  = c * 32 + kk;
        if (kk < 32 && k < CC) x = W1[((size_t)e * CC + k) * HH + h];
    } else {
        pos = idx - EE*7*128*40;
        if (pos >= EE*4*128*40) return;
        int kk = pos % 40;
        int h  = (pos / 40) % 128;
        int t  = pos / 5120;
        int c  = t % 4, e = t / 4;
        int k  = c * 32 + kk;
        if (kk < 32) x = W2[((size_t)e * HH + k) * HH + h];
    }
    unsigned u = __float_as_uint(x);
    unsigned short hi = (unsigned short)(u >> 16);
    float lo = x - __uint_as_float(u & 0xffff0000u);
    unsigned short lob;
    {
        unsigned p;
        asm("cvt.rn.bf16x2.f32 %0, %1, %2;" : "=r"(p) : "f"(0.f), "f"(lo));
        lob = (unsigned short)(p & 0xffffu);
    }
    if (dst_is_w1) { d_W1h[pos] = hi; d_W1l[pos] = lob; }
    else           { d_W2h[pos] = hi; d_W2l[pos] = lob; }
}

// single-pass scan (+ per-replay zeroing of accumulators)
__global__ void k_scan1() {
    __shared__ int ws[32];
    __shared__ int amLast;
    int b = blockIdx.x, t = threadIdx.x, i = b * 1024 + t;
    int lane = t & 31, w = t >> 5;
    int x = d_cnt[i];
    d_cnt[i] = 0;
    d_cur[i] = 0;
    if (i < 2*EH) { d_st1[i] = 0.f; d_st2[i] = 0.f; }
    if (i < EE) { d_imp[i] = 0.f; d_loadc[i] = 0.f; }
    if (i == 0) { d_tvsum = 0.f; d_off[NN] = 0; }
    int s = x;
#pragma unroll
    for (int o = 1; o < 32; o <<= 1) {
        int y = __shfl_up_sync(0xffffffffu, s, o);
        if (lane >= o) s += y;
    }
    if (lane == 31) ws[w] = s;
    __syncthreads();
    if (w == 0) {
        int ss = ws[lane];
#pragma unroll
        for (int o = 1; o < 32; o <<= 1) {
            int y = __shfl_up_sync(0xffffffffu, ss, o);
            if (lane >= o) ss += y;
        }
        ws[lane] = ss;
    }
    __syncthreads();
    int incl = s + (w ? ws[w-1] : 0);
    d_off[i] = incl - x;
    if (t == 1023) d_bsum[b] = incl;
    __threadfence();
    __syncthreads();
    if (t == 0) amLast = (atomicAdd(&d_scancnt, 1) == NSCAN_BLK - 1);
    __syncthreads();
    if (amLast) {
        int xb = 0, sb = 0;
        if (t < 64) {
            xb = (t < NSCAN_BLK) ? *((volatile int*)&d_bsum[t]) : 0;
            sb = xb;
#pragma unroll
            for (int o = 1; o < 32; o <<= 1) {
                int y = __shfl_up_sync(0xffffffffu, sb, o);
                if (lane >= o) sb += y;
            }
            if (lane == 31) ws[w] = sb;
        }
        __syncthreads();
        if (t < 64) {
            if (w == 1) sb += ws[0];
            d_bpre[t] = sb - xb;
        }
        if (t == 0) d_scancnt = 0;
    }
}

__global__ void k_scatter(const int* __restrict__ rows, const int* __restrict__ cols,
                          const float* __restrict__ vals) {
    int i = blockIdx.x * 256 + threadIdx.x;
    if (i >= NEDGE) return;
    int r = rows[i];
    int p = atomicAdd(&d_cur[r], 1);
    int d = d_off[r] + d_bpre[r >> 10] + p;
    d_ecol[d] = cols[i];
    d_eval[d] = vals[i];
}

// 4-edge unrolled gather-accumulate
__global__ void k_agg(const float* __restrict__ v) {
    int tid = threadIdx.x;
    int w = tid >> 5, lane = tid & 31;
    int n = blockIdx.x * 8 + w;
    float acc[7];
#pragma unroll
    for (int j = 0; j < 7; j++) acc[j] = 0.f;
    int s = d_off[n] + d_bpre[n >> 10];
    int e = d_off[n + 1] + d_bpre[(n + 1) >> 10];
    int k = s;
    for (; k + 3 < e; k += 4) {
        int c0 = d_ecol[k],   c1 = d_ecol[k+1], c2 = d_ecol[k+2], c3 = d_ecol[k+3];
        float v0 = d_eval[k], v1 = d_eval[k+1];
        float v2 = d_eval[k+2], v3 = d_eval[k+3];
        const float* p0 = v + (size_t)c0 * CC + lane;
        const float* p1 = v + (size_t)c1 * CC + lane;
        const float* p2 = v + (size_t)c2 * CC + lane;
        const float* p3 = v + (size_t)c3 * CC + lane;
#pragma unroll
        for (int j = 0; j < 6; j++)
            acc[j] += v0 * __ldg(p0 + 32*j) + v1 * __ldg(p1 + 32*j)
                    + v2 * __ldg(p2 + 32*j) + v3 * __ldg(p3 + 32*j);
        if (lane < 8)
            acc[6] += v0 * __ldg(p0 + 192) + v1 * __ldg(p1 + 192)
                    + v2 * __ldg(p2 + 192) + v3 * __ldg(p3 + 192);
    }
    for (; k < e; k++) {
        int c0 = d_ecol[k]; float v0 = d_eval[k];
        const float* p0 = v + (size_t)c0 * CC + lane;
#pragma unroll
        for (int j = 0; j < 6; j++) acc[j] += v0 * __ldg(p0 + 32*j);
        if (lane < 8) acc[6] += v0 * __ldg(p0 + 192);
    }
    float* op = d_agg + (size_t)n * CC + lane;
#pragma unroll
    for (int j = 0; j < 6; j++) op[32*j] = acc[j];
    if (lane < 8) op[192] = acc[6];
}

__global__ void k_gate(const float* __restrict__ v, const float* __restrict__ gW,
                       const float* __restrict__ gb) {
    __shared__ float sW[CC*EE];
    __shared__ float sImp[EE], sLoad[EE], sTv;
    int tid = threadIdx.x;
    for (int i = tid; i < CC*EE; i += 256) sW[i] = gW[i];
    if (tid < EE) { sImp[tid] = 0.f; sLoad[tid] = 0.f; }
    if (tid == 0) sTv = 0.f;
    __syncthreads();
    int w = tid >> 5, lane = tid & 31;
    int n = blockIdx.x * 8 + w;
    float acc[EE];
#pragma unroll
    for (int e = 0; e < EE; e++) acc[e] = 0.f;
    for (int c = lane; c < CC; c += 32) {
        float vv = v[n*CC + c];
#pragma unroll
        for (int e = 0; e < EE; e++) acc[e] += vv * sW[c*EE + e];
    }
#pragma unroll
    for (int e = 0; e < EE; e++)
        for (int o = 16; o; o >>= 1) acc[e] += __shfl_xor_sync(0xffffffffu, acc[e], o);
    if (lane == 0) {
        float lg[EE];
        float lm = -1e30f; int li = 0;
#pragma unroll
        for (int e = 0; e < EE; e++) {
            lg[e] = acc[e] + gb[e];
            if (lg[e] > lm) { lm = lg[e]; li = e; }
        }
        float sum = 0.f; float p[EE];
#pragma unroll
        for (int e = 0; e < EE; e++) { p[e] = expf(lg[e] - lm); sum += p[e]; }
        float inv = 1.f / sum;
        d_topidx[n] = li;
        d_topval[n] = inv;
#pragma unroll
        for (int e = 0; e < EE; e++) atomicAdd(&sImp[e], p[e] * inv);
        atomicAdd(&sLoad[li], 1.f);
        atomicAdd(&sTv, inv);
    }
    __syncthreads();
    if (tid < EE) { atomicAdd(&d_imp[tid], sImp[tid]); atomicAdd(&d_loadc[tid], sLoad[tid]); }
    if (tid == 0) atomicAdd(&d_tvsum, sTv);
}

// ======================= mma consume: ldmatrix + 3x bf16-split =======================
__device__ __forceinline__ void mma_consume(unsigned smem_u, int stage, int wm, int wn,
                                            int lane, float acc[4][4][4]) {
    unsigned st = smem_u + (unsigned)stage * SM_STAGE;
    unsigned lrow = (unsigned)(lane & 15) * 80u + (unsigned)(lane >> 4) * 16u;
    unsigned aB  = st + SM_AH + (unsigned)(wm*64) * 80u + lrow;
    unsigned aBL = st + SM_AL + (unsigned)(wm*64) * 80u + lrow;
    unsigned bB  = st + SM_BH + (unsigned)(wn*32) * 80u + lrow;
    unsigned bBL = st + SM_BL + (unsigned)(wn*32) * 80u + lrow;
#pragma unroll
    for (int s = 0; s < 2; s++) {
        unsigned kb = (unsigned)s * 32u;
        unsigned ah[4][4], al[4][4], bh[4][2], bl[4][2];
#pragma unroll
        for (int i = 0; i < 4; i++) {
            LDSM_X4(ah[i][0], ah[i][1], ah[i][2], ah[i][3], aB  + (unsigned)i*1280u + kb);
            LDSM_X4(al[i][0], al[i][1], al[i][2], al[i][3], aBL + (unsigned)i*1280u + kb);
        }
#pragma unroll
        for (int jp = 0; jp < 2; jp++) {
            unsigned r0, r1, r2, r3;
            LDSM_X4(r0, r1, r2, r3, bB + (unsigned)jp*1280u + kb);
            bh[jp*2][0] = r0; bh[jp*2+1][0] = r1; bh[jp*2][1] = r2; bh[jp*2+1][1] = r3;
            LDSM_X4(r0, r1, r2, r3, bBL + (unsigned)jp*1280u + kb);
            bl[jp*2][0] = r0; bl[jp*2+1][0] = r1; bl[jp*2][1] = r2; bl[jp*2+1][1] = r3;
        }
#pragma unroll
        for (int j = 0; j < 4; j++) {
#pragma unroll
            for (int i = 0; i < 4; i++)
                mma_bf16(acc[i][j], ah[i][0], ah[i][1], ah[i][2], ah[i][3], bh[j][0], bh[j][1]);
#pragma unroll
            for (int i = 0; i < 4; i++)
                mma_bf16(acc[i][j], al[i][0], al[i][1], al[i][2], al[i][3], bh[j][0], bh[j][1]);
#pragma unroll
            for (int i = 0; i < 4; i++)
                mma_bf16(acc[i][j], ah[i][0], ah[i][1], ah[i][2], ah[i][3], bl[j][0], bl[j][1]);
        }
    }
}

// ======================= GEMM1 =======================
__global__ __launch_bounds__(256, 2) void k_mma1(const float* __restrict__ v,
                                                 const float* __restrict__ eps) {
    extern __shared__ char smem[];
    unsigned smem_u = (unsigned)__cvta_generic_to_shared(smem);
    int tid = threadIdx.x, wid = tid >> 5, lane = tid & 31;
    int e = blockIdx.y, n0 = blockIdx.x * 128;
    int wm = wid & 1, wn = wid >> 1;
    float s = 1.f + __ldg(eps + e);

    int r = tid >> 1, c0 = (tid & 1) * 16;
    const float* ap = d_agg + (size_t)(n0 + r) * CC;
    const float* vp = v     + (size_t)(n0 + r) * CC;

    float acc[4][4][4];
#pragma unroll
    for (int i = 0; i < 4; i++)
#pragma unroll
        for (int j = 0; j < 4; j++)
#pragma unroll
            for (int q = 0; q < 4; q++) acc[i][j][q] = 0.f;

    float4 ra[4], rv[4];

#define LOADA1(cc) do {                                                           \
    int kc = (cc) * 32;                                                           \
    _Pragma("unroll")                                                             \
    for (int g4 = 0; g4 < 4; g4++) {                                              \
        int k = kc + c0 + g4*4;                                                   \
        if (k < CC) { ra[g4] = *(const float4*)(ap + k);                          \
                      rv[g4] = *(const float4*)(vp + k); }                        \
        else { ra[g4] = make_float4(0.f,0.f,0.f,0.f);                             \
               rv[g4] = make_float4(0.f,0.f,0.f,0.f); }                           \
    }                                                                             \
} while (0)

#define STOREA1(cc) do {                                                          \
    int stg = (cc) & 1;                                                           \
    unsigned* sAh = (unsigned*)(smem + stg*SM_STAGE + SM_AH);                     \
    unsigned* sAl = (unsigned*)(smem + stg*SM_STAGE + SM_AL);                     \
    _Pragma("unroll")                                                             \
    for (int g4 = 0; g4 < 4; g4++) {                                              \
        int idx = r*20 + ((c0 + g4*4) >> 1);                                      \
        split4_store(sAh, sAl, idx,                                               \
                     ra[g4].x + s*rv[g4].x, ra[g4].y + s*rv[g4].y,                \
                     ra[g4].z + s*rv[g4].z, ra[g4].w + s*rv[g4].w);               \
    }                                                                             \
} while (0)

#define CPB1(cc) do {                                                             \
    int stg = (cc) & 1;                                                           \
    unsigned bhs = smem_u + stg*SM_STAGE + SM_BH;                                 \
    unsigned bls = smem_u + stg*SM_STAGE + SM_BL;                                 \
    const char* gbh = (const char*)(d_W1h + (size_t)(e*7 + (cc)) * 5120);         \
    const char* gbl = (const char*)(d_W1l + (size_t)(e*7 + (cc)) * 5120);         \
    _Pragma("unroll")                                                             \
    for (int ii = 0; ii < 3; ii++) {                                              \
        int i2 = tid + ii*256;                                                    \
        if (i2 < 640) {                                                           \
            CP_ASYNC16(bhs + i2*16, gbh + i2*16);                                 \
            CP_ASYNC16(bls + i2*16, gbl + i2*16);                                 \
        }                                                                         \
    }                                                                             \
    CP_COMMIT();                                                                  \
} while (0)

    LOADA1(0); CPB1(0); STOREA1(0);
    CP_WAIT0(); __syncthreads();
    LOADA1(1); CPB1(1);
    for (int c = 0; c < 7; c++) {
        mma_consume(smem_u, c & 1, wm, wn, lane, acc);
        if (c < 6) STOREA1(c + 1);
        CP_WAIT0();
        __syncthreads();
        if (c < 5) { LOADA1(c + 2); CPB1(c + 2); }
    }
#undef LOADA1
#undef STOREA1
#undef CPB1

    // epilogue: store h1, BN stats (bias omitted: cancels in BatchNorm)
    int g = lane >> 2, t = lane & 3;
    float sv[4][2], sq[4][2];
#pragma unroll
    for (int j = 0; j < 4; j++) { sv[j][0]=sv[j][1]=sq[j][0]=sq[j][1]=0.f; }
#pragma unroll
    for (int i = 0; i < 4; i++) {
        int row0 = n0 + wm*64 + i*16 + g;
#pragma unroll
        for (int j = 0; j < 4; j++) {
            float v0 = acc[i][j][0], v1 = acc[i][j][1];
            float v2 = acc[i][j][2], v3 = acc[i][j][3];
            int col = wn*32 + j*8 + 2*t;
            *(float2*)(d_h1 + ((size_t)e*NN + row0)*HH + col)     = make_float2(v0, v1);
            *(float2*)(d_h1 + ((size_t)e*NN + row0 + 8)*HH + col) = make_float2(v2, v3);
            sv[j][0] += v0 + v2; sv[j][1] += v1 + v3;
            sq[j][0] += v0*v0 + v2*v2; sq[j][1] += v1*v1 + v3*v3;
        }
    }
#pragma unroll
    for (int j = 0; j < 4; j++)
#pragma unroll
        for (int p = 0; p < 2; p++) {
#pragma unroll
            for (int o = 4; o < 32; o <<= 1) {
                sv[j][p] += __shfl_xor_sync(0xffffffffu, sv[j][p], o);
                sq[j][p] += __shfl_xor_sync(0xffffffffu, sq[j][p], o);
            }
        }
    if (g == 0) {
#pragma unroll
        for (int j = 0; j < 4; j++)
#pragma unroll
            for (int p = 0; p < 2; p++) {
                int col = wn*32 + j*8 + 2*t + p;
                atomicAdd(&d_st1[e*HH + col], sv[j][p]);
                atomicAdd(&d_st1[EH + e*HH + col], sq[j][p]);
            }
    }
}

__global__ void k_fin1(const float* __restrict__ g1, const float* __restrict__ be1) {
    int i = blockIdx.x * 256 + threadIdx.x;
    if (i >= EH) return;
    float mean = d_st1[i] / (float)NN;
    float var  = d_st1[EH + i] / (float)NN - mean * mean;
    float al = g1[i] * rsqrtf(var + 1e-5f);
    d_al1[i]  = al;
    d_bsh1[i] = be1[i] - mean * al;
}

// ======================= GEMM2 =======================
__global__ __launch_bounds__(256, 2) void k_mma2() {
    extern __shared__ char smem[];
    unsigned smem_u = (unsigned)__cvta_generic_to_shared(smem);
    int tid = threadIdx.x, wid = tid >> 5, lane = tid & 31;
    int e = blockIdx.y, n0 = blockIdx.x * 128;
    int wm = wid & 1, wn = wid >> 1;

    float* sAlv = (float*)(smem + SM_ALBS);
    float* sBsv = sAlv + 128;
    if (tid < 128) { sAlv[tid] = d_al1[e*HH + tid]; sBsv[tid] = d_bsh1[e*HH + tid]; }
    __syncthreads();

    int r = tid >> 1, c0 = (tid & 1) * 16;
    const float* hp = d_h1 + ((size_t)e * NN + n0 + r) * HH;

    float acc[4][4][4];
#pragma unroll
    for (int i = 0; i < 4; i++)
#pragma unroll
        for (int j = 0; j < 4; j++)
#pragma unroll
            for (int q = 0; q < 4; q++) acc[i][j][q] = 0.f;

    float4 rh[4];

#define LOADA2(cc) do {                                                           \
    int kc = (cc) * 32;                                                           \
    _Pragma("unroll")                                                             \
    for (int g4 = 0; g4 < 4; g4++) {                                              \
        int k = kc + c0 + g4*4;                                                   \
        rh[g4] = *(const float4*)(hp + k);                                        \
    }                                                                             \
} while (0)

#define STOREA2(cc) do {                                                          \
    int stg = (cc) & 1;                                                           \
    unsigned* sAh = (unsigned*)(smem + stg*SM_STAGE + SM_AH);                     \
    unsigned* sAl = (unsigned*)(smem + stg*SM_STAGE + SM_AL);                     \
    int kc = (cc) * 32;                                                           \
    _Pragma("unroll")                                                             \
    for (int g4 = 0; g4 < 4; g4++) {                                              \
        int k = kc + c0 + g4*4;                                                   \
        int idx = r*20 + ((c0 + g4*4) >> 1);                                      \
        float4 al = *(const float4*)(sAlv + k);                                   \
        float4 bs = *(const float4*)(sBsv + k);                                   \
        split4_store(sAh, sAl, idx,                                               \
                     fmaxf(al.x * rh[g4].x + bs.x, 0.f),                          \
                     fmaxf(al.y * rh[g4].y + bs.y, 0.f),                          \
                     fmaxf(al.z * rh[g4].z + bs.z, 0.f),                          \
                     fmaxf(al.w * rh[g4].w + bs.w, 0.f));                         \
    }                                                                             \
} while (0)

#define CPB2(cc) do {                                                             \
    int stg = (cc) & 1;                                                           \
    unsigned bhs = smem_u + stg*SM_STAGE + SM_BH;                                 \
    unsigned bls = smem_u + stg*SM_STAGE + SM_BL;                                 \
    const char* gbh = (const char*)(d_W2h + (size_t)(e*4 + (cc)) * 5120);         \
    const char* gbl = (const char*)(d_W2l + (size_t)(e*4 + (cc)) * 5120);         \
    _Pragma("unroll")                                                             \
    for (int ii = 0; ii < 3; ii++) {                                              \
        int i2 = tid + ii*256;                                                    \
        if (i2 < 640) {                                                           \
            CP_ASYNC16(bhs + i2*16, gbh + i2*16);                                 \
            CP_ASYNC16(bls + i2*16, gbl + i2*16);                                 \
        }                                                                         \
    }                                                                             \
    CP_COMMIT();                                                                  \
} while (0)

    LOADA2(0); CPB2(0); STOREA2(0);
    CP_WAIT0(); __syncthreads();
    LOADA2(1); CPB2(1);
    for (int c = 0; c < 4; c++) {
        mma_consume(smem_u, c & 1, wm, wn, lane, acc);
        if (c < 3) STOREA2(c + 1);
        CP_WAIT0();
        __syncthreads();
        if (c < 2) { LOADA2(c + 2); CPB2(c + 2); }
    }
#undef LOADA2
#undef STOREA2
#undef CPB2

    int g = lane >> 2, t = lane & 3;
    float sv[4][2], sq[4][2];
#pragma unroll
    for (int j = 0; j < 4; j++) { sv[j][0]=sv[j][1]=sq[j][0]=sq[j][1]=0.f; }
#pragma unroll
    for (int i = 0; i < 4; i++) {
        int row0 = n0 + wm*64 + i*16 + g;
        bool sel0 = (d_topidx[row0] == e);
        bool sel8 = (d_topidx[row0 + 8] == e);
#pragma unroll
        for (int j = 0; j < 4; j++) {
            float v0 = acc[i][j][0], v1 = acc[i][j][1];
            float v2 = acc[i][j][2], v3 = acc[i][j][3];
            int col = wn*32 + j*8 + 2*t;
            if (sel0) *(float2*)(d_h2sel + (size_t)row0*HH + col)       = make_float2(v0, v1);
            if (sel8) *(float2*)(d_h2sel + (size_t)(row0 + 8)*HH + col) = make_float2(v2, v3);
            sv[j][0] += v0 + v2; sv[j][1] += v1 + v3;
            sq[j][0] += v0*v0 + v2*v2; sq[j][1] += v1*v1 + v3*v3;
        }
    }
#pragma unroll
    for (int j = 0; j < 4; j++)
#pragma unroll
        for (int p = 0; p < 2; p++) {
#pragma unroll
            for (int o = 4; o < 32; o <<= 1) {
                sv[j][p] += __shfl_xor_sync(0xffffffffu, sv[j][p], o);
                sq[j][p] += __shfl_xor_sync(0xffffffffu, sq[j][p], o);
            }
        }
    if (g == 0) {
#pragma unroll
        for (int j = 0; j < 4; j++)
#pragma unroll
            for (int p = 0; p < 2; p++) {
                int col = wn*32 + j*8 + 2*t + p;
                atomicAdd(&d_st2[e*HH + col], sv[j][p]);
                atomicAdd(&d_st2[EH + e*HH + col], sq[j][p]);
            }
    }
}

__global__ void k_fin2(const float* __restrict__ g2, const float* __restrict__ be2,
                       float* __restrict__ out, int out_size) {
    int i = blockIdx.x * 256 + threadIdx.x;
    if (i < EH) {
        float mean = d_st2[i] / (float)NN;
        float var  = d_st2[EH + i] / (float)NN - mean * mean;
        float al = g2[i] * rsqrtf(var + 1e-5f);
        d_al2[i]  = al;
        d_bsh2[i] = be2[i] - mean * al;
    }
    if (i == 0) {
        float bal = 0.f;
        for (int e = 0; e < EE; e++)
            bal += (d_imp[e] / (float)NN) * (d_loadc[e] / (float)NN);
        bal *= 0.01f * (float)EE;
        float spa = -0.01f * d_tvsum / (float)NN;
        if (out_size >= NN*HH + 2) {
            out[NN*HH]     = bal;
            out[NN*HH + 1] = spa;
        }
    }
}

__global__ void k_comb(float* __restrict__ out) {
    int idx = blockIdx.x * 256 + threadIdx.x;
    int n = idx >> 7, h = idx & 127;
    int e = d_topidx[n];
    float x = d_h2sel[idx];
    float r = fmaxf(d_al2[e*HH + h] * x + d_bsh2[e*HH + h], 0.f);
    out[idx] = d_topval[n] * r;
}

extern "C" void kernel_launch(void* const* d_in, const int* in_sizes, int n_in,
                              void* d_out, int out_size) {
    (void)in_sizes; (void)n_in;
    const float* v     = (const float*)d_in[0];
    const int*   arows = (const int*)  d_in[1];
    const int*   acols = (const int*)  d_in[2];
    const float* avals = (const float*)d_in[3];
    const float* gW    = (const float*)d_in[4];
    const float* gb    = (const float*)d_in[5];
    const float* eps   = (const float*)d_in[6];
    const float* W1    = (const float*)d_in[7];
    const float* g1    = (const float*)d_in[9];
    const float* be1   = (const float*)d_in[10];
    const float* W2    = (const float*)d_in[11];
    const float* g2    = (const float*)d_in[13];
    const float* be2   = (const float*)d_in[14];
    float* out = (float*)d_out;

    cudaFuncSetAttribute(k_mma1, cudaFuncAttributeMaxDynamicSharedMemorySize, SMEM_MMA);
    cudaFuncSetAttribute(k_mma2, cudaFuncAttributeMaxDynamicSharedMemorySize, SMEM_MMA);

    k_pre<<<CNT_BLOCKS + TR_BLOCKS, 256>>>(arows, W1, W2);                 // 0
    k_scan1<<<NSCAN_BLK, 1024>>>();                                        // 1
    k_scatter<<<NEDGE/256, 256>>>(arows, acols, avals);                    // 2
    k_agg<<<NN/8, 256>>>(v);                                               // 3  <- profiled
    {
        dim3 g(NN/128, EE);
        k_mma1<<<g, 256, SMEM_MMA>>>(v, eps);                              // 4
    }
    k_gate<<<NN/8, 256>>>(v, gW, gb);                                      // 5
    k_fin1<<<(EH + 255)/256, 256>>>(g1, be1);                              // 6
    {
        dim3 g(NN/128, EE);
        k_mma2<<<g, 256, SMEM_MMA>>>();                                    // 7
    }
    k_fin2<<<(EH + 255)/256, 256>>>(g2, be2, out, out_size);               // 8
    k_comb<<<(NN*HH)/256, 256>>>(out);                                     // 9
}